// round 4
// baseline (speedup 1.0000x reference)
#include <cuda_runtime.h>
#include <cuda_fp16.h>
#include <math.h>
#include <stdint.h>

// Problem constants
#define BQ   32      // batch
#define CINC 64      // input channels
#define HH   32      // height
#define WW   128     // width
#define OCC  128     // output channels
#define G5   640     // 5*OC gate width
#define KKK  320     // GEMM K = 128 (h_up) + 128 (h_lf) + 64 (x)
#define NDIR 4

#define MTILE 128    // GEMM M tile (4 cells x 32 batch)
#define NTILE 160    // GEMM N tile (5 gates x 32 channels, permuted)
#define AKH   328    // padded K stride (halves) for smem tiles
#define CPAD  164    // padded stride (floats) for C smem

#define SMEM_BYTES ((MTILE + NTILE) * AKH * 2)   // 188,928 B

// -------- device scratch (static allocation; no cudaMalloc allowed) --------
__device__ __half d_xT16[HH][WW][BQ][CINC];          // 16 MB, x transposed fp16
__device__ __half d_BpT[NDIR][G5][KKK];              // 1.6 MB, permuted weights, N-major
__device__ float  d_biasP[NDIR][G5];                 // permuted bias (fp32)
__device__ __half d_h16[NDIR][HH][WW][BQ][OCC];      // 128 MB, h state fp16 (GEMM operand)
__device__ float  d_h32[NDIR][HH][WW][BQ][OCC];      // 256 MB, h state fp32 (output source)
__device__ float  d_c32[NDIR][HH][WW][BQ][OCC];      // 256 MB, c state fp32

// ---------------------------------------------------------------------------
// prep kernels
// ---------------------------------------------------------------------------
__global__ void prep_x(const float* __restrict__ x) {
    int i = blockIdx.x * blockDim.x + threadIdx.x;
    if (i >= HH * WW * BQ * CINC) return;
    int cin = i & 63;
    int b   = (i >> 6) & 31;
    int xw  = (i >> 11) & 127;
    int y   = i >> 18;
    ((__half*)d_xT16)[i] = __float2half(x[((b * CINC + cin) * HH + y) * WW + xw]);
}

__global__ void prep_w(const float* __restrict__ w0,
                       const float* __restrict__ u0,
                       const float* __restrict__ u1) {
    int i = blockIdx.x * blockDim.x + threadIdx.x;
    if (i >= NDIR * G5 * KKK) return;
    int k    = i % KKK;
    int pcol = (i / KKK) % G5;
    int d    = i / (G5 * KKK);
    int cbl  = pcol / NTILE;
    int rem  = pcol % NTILE;
    int gate = rem / 32;
    int lane = rem % 32;
    int gcol = gate * 128 + cbl * 32 + lane;   // original gate column
    float v;
    if (k < 128)        v = u0[(d * 128 + k) * G5 + gcol];
    else if (k < 256)   v = u1[(d * 128 + (k - 128)) * G5 + gcol];
    else                v = w0[(d * 64  + (k - 256)) * G5 + gcol];
    ((__half*)d_BpT)[i] = __float2half(v);
}

__global__ void prep_b(const float* __restrict__ bias) {
    int i = blockIdx.x * blockDim.x + threadIdx.x;
    if (i >= NDIR * G5) return;
    int pcol = i % G5;
    int d    = i / G5;
    int cbl  = pcol / NTILE;
    int rem  = pcol % NTILE;
    int gate = rem / 32;
    int lane = rem % 32;
    int gcol = gate * 128 + cbl * 32 + lane;
    d_biasP[d][pcol] = bias[d * G5 + gcol];
}

// ---------------------------------------------------------------------------
// one anti-diagonal wavefront: GEMM (fp16 HMMA, fp32 accum) + LSTM epilogue
// grid: (ceil(len/4), 4 channel-blocks, 4 directions), block: 256 threads
// ---------------------------------------------------------------------------
__device__ __forceinline__ float sigmoidf_(float v) {
    return 1.0f / (1.0f + expf(-v));
}

__global__ void __launch_bounds__(256, 1) diag_kernel(int t) {
    int y0 = t - (WW - 1); if (y0 < 0) y0 = 0;
    int y1 = (t < HH - 1) ? t : (HH - 1);
    const int len   = y1 - y0 + 1;
    const int mtile = blockIdx.x;
    const int cb    = blockIdx.y;
    const int d     = blockIdx.z;

    extern __shared__ __align__(16) char smem_raw[];
    __half* As  = (__half*)smem_raw;              // [128][AKH] halves
    __half* Bs  = As + MTILE * AKH;               // [160][AKH] halves (N-major)
    float*  Csm = (float*)smem_raw;               // [128][CPAD] floats, reuses As

    const int tid = threadIdx.x;

    // ---- stage A tile: rows = (cell, batch), cols = [h_up | h_lf | x] ----
    for (int c = tid; c < MTILE * 40; c += 256) {
        int r  = c / 40;
        int q  = c - r * 40;         // which uint4 (8 halves) of the 320-half row
        int cl = r >> 5, b = r & 31;
        int cell = mtile * 4 + cl;
        uint4 v = make_uint4(0u, 0u, 0u, 0u);
        if (cell < len) {
            int y  = y0 + cell;
            int xw = t - y;
            int k  = q * 8;
            if (k < 128) {
                if (y > 0) v = *(const uint4*)&d_h16[d][y - 1][xw][b][k];
            } else if (k < 256) {
                if (xw > 0) v = *(const uint4*)&d_h16[d][y][xw - 1][b][k - 128];
            } else {
                int fy = (d & 2) ? (HH - 1 - y)  : y;
                int fx = (d & 1) ? (WW - 1 - xw) : xw;
                v = *(const uint4*)&d_xT16[fy][fx][b][k - 256];
            }
        }
        *(uint4*)&As[r * AKH + q * 8] = v;
    }
    // ---- stage B slice (already permuted + N-major in global) ----
    for (int c = tid; c < NTILE * 40; c += 256) {
        int n = c / 40;
        int q = c - n * 40;
        *(uint4*)&Bs[n * AKH + q * 8] =
            *(const uint4*)&d_BpT[d][cb * NTILE + n][q * 8];
    }
    __syncthreads();

    // ---- MMA mainloop: 8 warps = 4 (M) x 2 (N); warp tile 32 x 80 ----
    const int warp = tid >> 5;
    const int lane = tid & 31;
    const int wm = warp & 3;      // row block: wm*32
    const int wn = warp >> 2;     // col block: wn*80
    const int g  = lane >> 2;
    const int tq = lane & 3;

    float acc[2][10][4];
#pragma unroll
    for (int mi = 0; mi < 2; mi++)
#pragma unroll
        for (int ni = 0; ni < 10; ni++)
#pragma unroll
            for (int e = 0; e < 4; e++) acc[mi][ni][e] = 0.0f;

    const __half* Abase = &As[(wm * 32 + g) * AKH + tq * 2];
    const __half* Bbase = &Bs[(wn * 80 + g) * AKH + tq * 2];

#pragma unroll 2
    for (int ks = 0; ks < 20; ks++) {
        const int k0 = ks * 16;
        uint32_t afr[2][4];
#pragma unroll
        for (int mi = 0; mi < 2; mi++) {
            const __half* p = Abase + mi * 16 * AKH + k0;
            afr[mi][0] = *(const uint32_t*)(p);
            afr[mi][1] = *(const uint32_t*)(p + 8 * AKH);
            afr[mi][2] = *(const uint32_t*)(p + 8);
            afr[mi][3] = *(const uint32_t*)(p + 8 * AKH + 8);
        }
#pragma unroll
        for (int ni = 0; ni < 10; ni++) {
            const __half* p = Bbase + ni * 8 * AKH + k0;
            uint32_t b0 = *(const uint32_t*)(p);
            uint32_t b1 = *(const uint32_t*)(p + 8);
#pragma unroll
            for (int mi = 0; mi < 2; mi++) {
                asm volatile(
                    "mma.sync.aligned.m16n8k16.row.col.f32.f16.f16.f32 "
                    "{%0,%1,%2,%3}, {%4,%5,%6,%7}, {%8,%9}, {%0,%1,%2,%3};\n"
                    : "+f"(acc[mi][ni][0]), "+f"(acc[mi][ni][1]),
                      "+f"(acc[mi][ni][2]), "+f"(acc[mi][ni][3])
                    : "r"(afr[mi][0]), "r"(afr[mi][1]),
                      "r"(afr[mi][2]), "r"(afr[mi][3]),
                      "r"(b0), "r"(b1));
            }
        }
    }
    __syncthreads();   // all warps done reading As before overwriting with Csm

    // ---- spill C to smem so the epilogue sees all 5 gates per channel ----
#pragma unroll
    for (int mi = 0; mi < 2; mi++) {
#pragma unroll
        for (int ni = 0; ni < 10; ni++) {
            int row = wm * 32 + mi * 16 + g;
            int col = wn * 80 + ni * 8 + tq * 2;
            *(float2*)&Csm[row * CPAD + col] =
                make_float2(acc[mi][ni][0], acc[mi][ni][1]);
            *(float2*)&Csm[(row + 8) * CPAD + col] =
                make_float2(acc[mi][ni][2], acc[mi][ni][3]);
        }
    }
    __syncthreads();

    // ---- LSTM epilogue (fp32): 128 rows x 32 channels ----
    for (int it = tid; it < MTILE * 32; it += 256) {
        int r = it >> 5;
        int j = it & 31;
        int cl = r >> 5, b = r & 31;
        int cell = mtile * 4 + cl;
        if (cell >= len) continue;
        int y  = y0 + cell;
        int xw = t - y;
        const float* cr = &Csm[r * CPAD];
        const float* bp = &d_biasP[d][cb * NTILE];
        float gi = cr[j]       + bp[j];
        float gf = cr[32 + j]  + bp[32 + j];
        float gg = cr[64 + j]  + bp[64 + j];
        float go = cr[96 + j]  + bp[96 + j];
        float gl = cr[128 + j] + bp[128 + j];
        float iv = sigmoidf_(gi);
        float fv = sigmoidf_(gf);
        float gv = tanhf(gg);
        float ov = sigmoidf_(go);
        float lv = sigmoidf_(gl);
        int oc = cb * 32 + j;
        float cup = (y  > 0) ? d_c32[d][y - 1][xw][b][oc] : 0.0f;
        float clf = (xw > 0) ? d_c32[d][y][xw - 1][b][oc] : 0.0f;
        float cn = fv * (lv * cup + (1.0f - lv) * clf) + iv * gv;
        float hn = ov * tanhf(cn);
        d_c32[d][y][xw][b][oc] = cn;
        d_h32[d][y][xw][b][oc] = hn;
        d_h16[d][y][xw][b][oc] = __float2half(hn);
    }
}

// ---------------------------------------------------------------------------
// final transpose: h32[d][y][xw][b][oc] -> out[b][d][oc][y][xw]
// block per (d, y, b, oc-chunk), smem 128x32 tile
// ---------------------------------------------------------------------------
__global__ void __launch_bounds__(256) finalize_kernel(float* __restrict__ out) {
    int bid = blockIdx.x;
    int occ = bid & 3;
    int b   = (bid >> 2) & 31;
    int y   = (bid >> 7) & 31;
    int d   = bid >> 12;

    __shared__ float sm[128][33];

    for (int i = threadIdx.x; i < 128 * 32; i += 256) {
        int xw = i >> 5;
        int j  = i & 31;
        sm[xw][j] = d_h32[d][y][xw][b][occ * 32 + j];
    }
    __syncthreads();
    for (int i = threadIdx.x; i < 32 * 128; i += 256) {
        int j  = i >> 7;        // channel lane
        int xw = i & 127;       // contiguous writes
        int oc = occ * 32 + j;
        out[(((size_t)(b * 4 + d) * OCC + oc) * HH + y) * WW + xw] = sm[xw][j];
    }
}

// ---------------------------------------------------------------------------
// launch
// ---------------------------------------------------------------------------
extern "C" void kernel_launch(void* const* d_in, const int* in_sizes, int n_in,
                              void* d_out, int out_size) {
    const float* x  = (const float*)d_in[0];
    const float* w0 = (const float*)d_in[1];
    const float* u0 = (const float*)d_in[2];
    const float* u1 = (const float*)d_in[3];
    const float* bb = (const float*)d_in[4];
    float* out = (float*)d_out;
    (void)in_sizes; (void)n_in; (void)out_size;

    cudaFuncSetAttribute(diag_kernel,
                         cudaFuncAttributeMaxDynamicSharedMemorySize, SMEM_BYTES);

    prep_x<<<(HH * WW * BQ * CINC + 255) / 256, 256>>>(x);
    prep_w<<<(NDIR * G5 * KKK + 255) / 256, 256>>>(w0, u0, u1);
    prep_b<<<(NDIR * G5 + 255) / 256, 256>>>(bb);

    for (int t = 0; t < HH + WW - 1; t++) {
        int y0 = t - (WW - 1); if (y0 < 0) y0 = 0;
        int y1 = (t < HH - 1) ? t : (HH - 1);
        int len = y1 - y0 + 1;
        dim3 grid((len + 3) / 4, 4, NDIR);
        diag_kernel<<<grid, 256, SMEM_BYTES>>>(t);
    }

    finalize_kernel<<<NDIR * HH * BQ * 4, 256>>>(out);
}

// round 5
// speedup vs baseline: 1.1248x; 1.1248x over previous
#include <cuda_runtime.h>
#include <cuda_fp16.h>
#include <math.h>
#include <stdint.h>

// Problem constants
#define BQ   32      // batch
#define CINC 64      // input channels
#define HH   32      // height
#define WW   128     // width
#define OCC  128     // output channels
#define G5   640     // 5*OC gate width
#define KKK  320     // GEMM K = 128 (h_up) + 128 (h_lf) + 64 (x)
#define NDIR 4
#define NDIAG (HH + WW - 1)   // 159

#define MTILE 128    // GEMM M tile (4 cells x 32 batch)
#define NTILE 160    // GEMM N tile (5 gates x 32 channels, permuted)
#define AKH   328    // padded K stride (halves) for smem tiles
#define CPAD  164    // padded stride (floats) for C smem

// As(128x328 half) + Bs(160x328 half) + bias(160 f32)
#define SMEM_BYTES ((MTILE + NTILE) * AKH * 2 + NTILE * 4)   // 189,568 B

// -------- device scratch (static allocation; no cudaMalloc allowed) --------
__device__ __half d_xT16[HH][WW][BQ][CINC];          // x transposed fp16
__device__ __half d_BpT[NDIR][G5][KKK];              // permuted weights, N-major
__device__ float  d_biasP[NDIR][G5];                 // permuted bias (fp32)
__device__ __half d_h16[NDIR][HH][WW][BQ][OCC];      // h state fp16 (GEMM operand)
__device__ float  d_h32[NDIR][HH][WW][BQ][OCC];      // h state fp32 (output source)
__device__ float  d_c32[NDIR][HH][WW][BQ][OCC];      // c state fp32
__device__ int    d_bar[NDIR * 32];                  // per-dir barrier, padded lines

// ---------------------------------------------------------------------------
// prep kernels
// ---------------------------------------------------------------------------
__global__ void prep_x(const float* __restrict__ x) {
    int i = blockIdx.x * blockDim.x + threadIdx.x;
    if (i >= HH * WW * BQ * CINC) return;
    int cin = i & 63;
    int b   = (i >> 6) & 31;
    int xw  = (i >> 11) & 127;
    int y   = i >> 18;
    ((__half*)d_xT16)[i] = __float2half(x[((b * CINC + cin) * HH + y) * WW + xw]);
}

__global__ void prep_w(const float* __restrict__ w0,
                       const float* __restrict__ u0,
                       const float* __restrict__ u1) {
    int i = blockIdx.x * blockDim.x + threadIdx.x;
    if (i >= NDIR * G5 * KKK) return;
    int k    = i % KKK;
    int pcol = (i / KKK) % G5;
    int d    = i / (G5 * KKK);
    int cbl  = pcol / NTILE;
    int rem  = pcol % NTILE;
    int gate = rem / 32;
    int lane = rem % 32;
    int gcol = gate * 128 + cbl * 32 + lane;   // original gate column
    float v;
    if (k < 128)        v = u0[(d * 128 + k) * G5 + gcol];
    else if (k < 256)   v = u1[(d * 128 + (k - 128)) * G5 + gcol];
    else                v = w0[(d * 64  + (k - 256)) * G5 + gcol];
    ((__half*)d_BpT)[i] = __float2half(v);
}

__global__ void prep_b(const float* __restrict__ bias) {
    int i = blockIdx.x * blockDim.x + threadIdx.x;
    if (i < NDIR * 32) d_bar[i] = 0;           // reset barrier every replay
    if (i >= NDIR * G5) return;
    int pcol = i % G5;
    int d    = i / G5;
    int cbl  = pcol / NTILE;
    int rem  = pcol % NTILE;
    int gate = rem / 32;
    int lane = rem % 32;
    int gcol = gate * 128 + cbl * 32 + lane;
    d_biasP[d][pcol] = bias[d * G5 + gcol];
}

__device__ __forceinline__ float sigmoidf_(float v) {
    return 1.0f / (1.0f + expf(-v));
}

// ---------------------------------------------------------------------------
// persistent wavefront kernel: grid = 128 CTAs (4 dir x 4 cb x 8 m-slots),
// 1 CTA/SM (forced by smem), all co-resident -> device-side diagonal loop
// with per-direction 32-CTA spin barriers.
// ---------------------------------------------------------------------------
__global__ void __launch_bounds__(256, 1) persist_kernel() {
    const int bid   = blockIdx.x;
    const int d     = bid >> 5;          // direction
    const int cb    = (bid >> 3) & 3;    // channel block (32 oc)
    const int mtile = bid & 7;           // m-slot (4 cells)
    const int tid   = threadIdx.x;

    extern __shared__ __align__(16) char smem_raw[];
    __half* As  = (__half*)smem_raw;                 // [128][AKH] halves
    __half* Bs  = As + MTILE * AKH;                  // [160][AKH] halves
    float*  bsm = (float*)(Bs + NTILE * AKH);        // [160] bias
    float*  Csm = (float*)smem_raw;                  // [128][CPAD], overlaps As

    // ---- stage B slice + bias ONCE (reused across all 159 diagonals) ----
    for (int c = tid; c < NTILE * 40; c += 256) {
        int n = c / 40;
        int q = c - n * 40;
        *(uint4*)&Bs[n * AKH + q * 8] =
            *(const uint4*)&d_BpT[d][cb * NTILE + n][q * 8];
    }
    for (int i = tid; i < NTILE; i += 256) bsm[i] = d_biasP[d][cb * NTILE + i];

    const int warp = tid >> 5;
    const int lane = tid & 31;
    const int wm = warp & 3;
    const int wn = warp >> 2;
    const int g  = lane >> 2;
    const int tq = lane & 3;
    const __half* Abase = &As[(wm * 32 + g) * AKH + tq * 2];
    const __half* Bbase = &Bs[(wn * 80 + g) * AKH + tq * 2];

    for (int t = 0; t < NDIAG; t++) {
        int y0 = t - (WW - 1); if (y0 < 0) y0 = 0;
        int y1 = (t < HH - 1) ? t : (HH - 1);
        const int len = y1 - y0 + 1;

        // ---- stage A tile: rows = (cell, batch), cols = [h_up | h_lf | x] ----
        for (int c = tid; c < MTILE * 40; c += 256) {
            int r  = c / 40;
            int q  = c - r * 40;
            int cl = r >> 5, b = r & 31;
            int cell = mtile * 4 + cl;
            uint4 v = make_uint4(0u, 0u, 0u, 0u);
            if (cell < len) {
                int y  = y0 + cell;
                int xw = t - y;
                int k  = q * 8;
                if (k < 128) {
                    if (y > 0) v = *(const uint4*)&d_h16[d][y - 1][xw][b][k];
                } else if (k < 256) {
                    if (xw > 0) v = *(const uint4*)&d_h16[d][y][xw - 1][b][k - 128];
                } else {
                    int fy = (d & 2) ? (HH - 1 - y)  : y;
                    int fx = (d & 1) ? (WW - 1 - xw) : xw;
                    v = *(const uint4*)&d_xT16[fy][fx][b][k - 256];
                }
            }
            *(uint4*)&As[r * AKH + q * 8] = v;
        }
        __syncthreads();

        // ---- MMA mainloop: 8 warps = 4(M) x 2(N); warp tile 32 x 80 ----
        float acc[2][10][4];
#pragma unroll
        for (int mi = 0; mi < 2; mi++)
#pragma unroll
            for (int ni = 0; ni < 10; ni++)
#pragma unroll
                for (int e = 0; e < 4; e++) acc[mi][ni][e] = 0.0f;

#pragma unroll 2
        for (int ks = 0; ks < 20; ks++) {
            const int k0 = ks * 16;
            uint32_t afr[2][4];
#pragma unroll
            for (int mi = 0; mi < 2; mi++) {
                const __half* p = Abase + mi * 16 * AKH + k0;
                afr[mi][0] = *(const uint32_t*)(p);
                afr[mi][1] = *(const uint32_t*)(p + 8 * AKH);
                afr[mi][2] = *(const uint32_t*)(p + 8);
                afr[mi][3] = *(const uint32_t*)(p + 8 * AKH + 8);
            }
#pragma unroll
            for (int ni = 0; ni < 10; ni++) {
                const __half* p = Bbase + ni * 8 * AKH + k0;
                uint32_t b0 = *(const uint32_t*)(p);
                uint32_t b1 = *(const uint32_t*)(p + 8);
#pragma unroll
                for (int mi = 0; mi < 2; mi++) {
                    asm volatile(
                        "mma.sync.aligned.m16n8k16.row.col.f32.f16.f16.f32 "
                        "{%0,%1,%2,%3}, {%4,%5,%6,%7}, {%8,%9}, {%0,%1,%2,%3};\n"
                        : "+f"(acc[mi][ni][0]), "+f"(acc[mi][ni][1]),
                          "+f"(acc[mi][ni][2]), "+f"(acc[mi][ni][3])
                        : "r"(afr[mi][0]), "r"(afr[mi][1]),
                          "r"(afr[mi][2]), "r"(afr[mi][3]),
                          "r"(b0), "r"(b1));
                }
            }
        }
        __syncthreads();   // done reading As before overwriting with Csm

        // ---- spill C to smem so epilogue sees all 5 gates per channel ----
#pragma unroll
        for (int mi = 0; mi < 2; mi++) {
#pragma unroll
            for (int ni = 0; ni < 10; ni++) {
                int row = wm * 32 + mi * 16 + g;
                int col = wn * 80 + ni * 8 + tq * 2;
                *(float2*)&Csm[row * CPAD + col] =
                    make_float2(acc[mi][ni][0], acc[mi][ni][1]);
                *(float2*)&Csm[(row + 8) * CPAD + col] =
                    make_float2(acc[mi][ni][2], acc[mi][ni][3]);
            }
        }
        __syncthreads();

        // ---- LSTM epilogue (fp32): 128 rows x 32 channels ----
        for (int it = tid; it < MTILE * 32; it += 256) {
            int r = it >> 5;
            int j = it & 31;
            int cl = r >> 5, b = r & 31;
            int cell = mtile * 4 + cl;
            if (cell >= len) continue;
            int y  = y0 + cell;
            int xw = t - y;
            const float* cr = &Csm[r * CPAD];
            float gi = cr[j]       + bsm[j];
            float gf = cr[32 + j]  + bsm[32 + j];
            float gg = cr[64 + j]  + bsm[64 + j];
            float go = cr[96 + j]  + bsm[96 + j];
            float gl = cr[128 + j] + bsm[128 + j];
            float iv = sigmoidf_(gi);
            float fv = sigmoidf_(gf);
            float gv = tanhf(gg);
            float ov = sigmoidf_(go);
            float lv = sigmoidf_(gl);
            int oc = cb * 32 + j;
            float cup = (y  > 0) ? d_c32[d][y - 1][xw][b][oc] : 0.0f;
            float clf = (xw > 0) ? d_c32[d][y][xw - 1][b][oc] : 0.0f;
            float cn = fv * (lv * cup + (1.0f - lv) * clf) + iv * gv;
            float hn = ov * tanhf(cn);
            d_c32[d][y][xw][b][oc] = cn;
            d_h32[d][y][xw][b][oc] = hn;
            d_h16[d][y][xw][b][oc] = __float2half(hn);
        }
        __syncthreads();   // all CTA threads done with global state writes

        // ---- per-direction barrier: release -> arrive -> spin -> acquire ----
        if (tid == 0) {
            __threadfence();                       // release state writes
            atomicAdd(&d_bar[d * 32], 1);
            const int target = 32 * (t + 1);
            while (((volatile int*)d_bar)[d * 32] < target) { }
            __threadfence();                       // acquire peers' writes
        }
        __syncthreads();
    }
}

// ---------------------------------------------------------------------------
// final transpose: h32[d][y][xw][b][oc] -> out[b][d][oc][y][xw]
// ---------------------------------------------------------------------------
__global__ void __launch_bounds__(256) finalize_kernel(float* __restrict__ out) {
    int bid = blockIdx.x;
    int occ = bid & 3;
    int b   = (bid >> 2) & 31;
    int y   = (bid >> 7) & 31;
    int d   = bid >> 12;

    __shared__ float sm[128][33];

    for (int i = threadIdx.x; i < 128 * 32; i += 256) {
        int xw = i >> 5;
        int j  = i & 31;
        sm[xw][j] = d_h32[d][y][xw][b][occ * 32 + j];
    }
    __syncthreads();
    for (int i = threadIdx.x; i < 32 * 128; i += 256) {
        int j  = i >> 7;        // channel lane
        int xw = i & 127;       // contiguous writes
        int oc = occ * 32 + j;
        out[(((size_t)(b * 4 + d) * OCC + oc) * HH + y) * WW + xw] = sm[xw][j];
    }
}

// ---------------------------------------------------------------------------
// launch
// ---------------------------------------------------------------------------
extern "C" void kernel_launch(void* const* d_in, const int* in_sizes, int n_in,
                              void* d_out, int out_size) {
    const float* x  = (const float*)d_in[0];
    const float* w0 = (const float*)d_in[1];
    const float* u0 = (const float*)d_in[2];
    const float* u1 = (const float*)d_in[3];
    const float* bb = (const float*)d_in[4];
    float* out = (float*)d_out;
    (void)in_sizes; (void)n_in; (void)out_size;

    cudaFuncSetAttribute(persist_kernel,
                         cudaFuncAttributeMaxDynamicSharedMemorySize, SMEM_BYTES);

    prep_x<<<(HH * WW * BQ * CINC + 255) / 256, 256>>>(x);
    prep_w<<<(NDIR * G5 * KKK + 255) / 256, 256>>>(w0, u0, u1);
    prep_b<<<(NDIR * G5 + 255) / 256, 256>>>(bb);

    persist_kernel<<<128, 256, SMEM_BYTES>>>();

    finalize_kernel<<<NDIR * HH * BQ * 4, 256>>>(out);
}

// round 6
// speedup vs baseline: 2.2137x; 1.9681x over previous
#include <cuda_runtime.h>
#include <cuda_fp16.h>
#include <math.h>
#include <stdint.h>

// Problem constants
#define BQ   32
#define CINC 64
#define HH   32
#define WW   128
#define OCC  128
#define G5   640
#define KKK  320     // K = 128 (h_up) + 128 (h_lf) + 64 (x)
#define NDIR 4
#define NDIAG (HH + WW - 1)   // 159

#define MTILE 128    // 4 cells x 32 batch
#define NTILE 160    // 5 gates x 32 channels (permuted)
#define AKH   328    // padded K stride (halves)
#define CPAD  164    // padded C stride (floats)

#define SMEM_BYTES ((MTILE + NTILE) * AKH * 2 + NTILE * 4)   // 189,568 B

// -------- device scratch --------
__device__ __half d_xT16[HH][WW][BQ][CINC];
__device__ __half d_BpT[NDIR][G5][KKK];
__device__ float  d_biasP[NDIR][G5];
__device__ __half d_h16[NDIR][HH][WW][BQ][OCC];
__device__ float  d_h32[NDIR][HH][WW][BQ][OCC];
__device__ float  d_c32[NDIR][HH][WW][BQ][OCC];
__device__ int    d_bar[NDIR * 32];

// ---------------------------------------------------------------------------
// prep kernels
// ---------------------------------------------------------------------------
__global__ void prep_x(const float* __restrict__ x) {
    int i = blockIdx.x * blockDim.x + threadIdx.x;
    if (i >= HH * WW * BQ * CINC) return;
    int cin = i & 63;
    int b   = (i >> 6) & 31;
    int xw  = (i >> 11) & 127;
    int y   = i >> 18;
    ((__half*)d_xT16)[i] = __float2half(x[((b * CINC + cin) * HH + y) * WW + xw]);
}

__global__ void prep_w(const float* __restrict__ w0,
                       const float* __restrict__ u0,
                       const float* __restrict__ u1) {
    int i = blockIdx.x * blockDim.x + threadIdx.x;
    if (i >= NDIR * G5 * KKK) return;
    int k    = i % KKK;
    int pcol = (i / KKK) % G5;
    int d    = i / (G5 * KKK);
    int cbl  = pcol / NTILE;
    int rem  = pcol % NTILE;
    int gate = rem / 32;
    int lane = rem % 32;
    int gcol = gate * 128 + cbl * 32 + lane;
    float v;
    if (k < 128)        v = u0[(d * 128 + k) * G5 + gcol];
    else if (k < 256)   v = u1[(d * 128 + (k - 128)) * G5 + gcol];
    else                v = w0[(d * 64  + (k - 256)) * G5 + gcol];
    ((__half*)d_BpT)[i] = __float2half(v);
}

__global__ void prep_b(const float* __restrict__ bias) {
    int i = blockIdx.x * blockDim.x + threadIdx.x;
    if (i < NDIR * 32) d_bar[i] = 0;           // reset barrier every replay
    if (i >= NDIR * G5) return;
    int pcol = i % G5;
    int d    = i / G5;
    int cbl  = pcol / NTILE;
    int rem  = pcol % NTILE;
    int gate = rem / 32;
    int lane = rem % 32;
    int gcol = gate * 128 + cbl * 32 + lane;
    d_biasP[d][pcol] = bias[d * G5 + gcol];
}

// ---------------------------------------------------------------------------
// fast device math
// ---------------------------------------------------------------------------
__device__ __forceinline__ float sig_f(float x) {
    return __fdividef(1.0f, 1.0f + __expf(-x));
}
__device__ __forceinline__ float tanh_f(float x) {
    float xc = fminf(fmaxf(x, -9.0f), 9.0f);
    float t  = __expf(2.0f * xc);
    return __fdividef(t - 1.0f, t + 1.0f);
}

__device__ __forceinline__ uint32_t smem_u32(const void* p) {
    return (uint32_t)__cvta_generic_to_shared(p);
}
__device__ __forceinline__ void ldsm_x4(uint32_t& r0, uint32_t& r1,
                                        uint32_t& r2, uint32_t& r3,
                                        uint32_t addr) {
    asm volatile("ldmatrix.sync.aligned.m8n8.x4.shared.b16 {%0,%1,%2,%3}, [%4];"
                 : "=r"(r0), "=r"(r1), "=r"(r2), "=r"(r3) : "r"(addr));
}

// ---------------------------------------------------------------------------
// persistent wavefront kernel: 128 CTAs (4 dir x 4 cb x 8 m-slots), 1/SM
// ---------------------------------------------------------------------------
__global__ void __launch_bounds__(256, 1) persist_kernel() {
    const int bid   = blockIdx.x;
    const int d     = bid >> 5;
    const int cb    = (bid >> 3) & 3;
    const int mtile = bid & 7;
    const int tid   = threadIdx.x;

    extern __shared__ __align__(16) char smem_raw[];
    __half* As  = (__half*)smem_raw;                 // [128][AKH]
    __half* Bs  = As + MTILE * AKH;                  // [160][AKH]
    float*  bsm = (float*)(Bs + NTILE * AKH);        // [160]
    float*  Csm = (float*)smem_raw;                  // [128][CPAD], overlaps As

    // ---- stage B slice + bias ONCE ----
    for (int c = tid; c < NTILE * 40; c += 256) {
        int n = c / 40;
        int q = c - n * 40;
        *(uint4*)&Bs[n * AKH + q * 8] =
            *(const uint4*)&d_BpT[d][cb * NTILE + n][q * 8];
    }
    for (int i = tid; i < NTILE; i += 256) bsm[i] = d_biasP[d][cb * NTILE + i];

    const int warp  = tid >> 5;
    const int lane  = tid & 31;
    const int wm    = warp & 3;
    const int wn    = warp >> 2;
    const int g     = lane >> 2;
    const int tq    = lane & 3;
    const int lane7 = lane & 7;
    const int lb8   = (lane >> 3) & 1;
    const int lb16  = lane >> 4;

    // ldmatrix lane addresses (bytes advance by k0*2 each k-step)
    const uint32_t aAddr0 =
        smem_u32(&As[(wm * 32 + lane7 + lb8 * 8) * AKH + lb16 * 8]);
    const uint32_t aAddr1 = aAddr0 + 16 * AKH * 2;
    uint32_t bAddr[5];
#pragma unroll
    for (int n2 = 0; n2 < 5; n2++)
        bAddr[n2] = smem_u32(
            &Bs[(wn * 80 + n2 * 16 + lb16 * 8 + lane7) * AKH + lb8 * 8]);

    // A-stage phase-A constants (per-warp cell)
    const int clA = warp >> 1;           // this warp's cell slot (phase A)
    const int bA0 = (warp & 1) * 16;     // batch base for phase A rows

    for (int t = 0; t < NDIAG; t++) {
        int y0 = t - (WW - 1); if (y0 < 0) y0 = 0;
        int y1 = (t < HH - 1) ? t : (HH - 1);
        const int len = y1 - y0 + 1;

        // ================= A-stage =================
        // Phase A: recurrent K (k<256). Warp handles cell clA, rows bA0..bA0+15.
        {
            int cell  = mtile * 4 + clA;
            int y     = y0 + cell;
            int xw    = t - y;
            bool valid = (cell < len);
            bool up_ok = valid && (y > 0);
            bool lf_ok = valid && (xw > 0);
            // clamp for safe pointer formation (loads are predicated off)
            int yu = (y > 0) ? y - 1 : 0;
            int xl = (xw > 0) ? xw - 1 : 0;
            int yc = valid ? y : 0;
            int xc = (valid && xw >= 0) ? xw : 0;
            const __half* pUp = &d_h16[d][yu][xc][0][0];
            const __half* pLf = &d_h16[d][yc][xl][0][0];
            const int sel  = (lane >= 16);
            const __half* pSel = sel ? pLf : pUp;
            const bool  pok  = sel ? lf_ok : up_ok;
            const int   koff = (lane * 8) & 127;
#pragma unroll
            for (int i = 0; i < 16; i++) {
                int b = bA0 + i;
                int r = warp * 16 + i;            // = clA*32 + b
                uint4 v = make_uint4(0u, 0u, 0u, 0u);
                if (pok) v = __ldcg((const uint4*)(pSel + b * 128 + koff));
                *(uint4*)&As[r * AKH + lane * 8] = v;
            }
        }
        // Phase B: x slice (k in [256,320)). 4 iters, cell = mtile*4 + i.
        {
            int b  = tid >> 3;
            int q8 = tid & 7;
#pragma unroll
            for (int i = 0; i < 4; i++) {
                int cell = mtile * 4 + i;
                uint4 v = make_uint4(0u, 0u, 0u, 0u);
                if (cell < len) {
                    int y  = y0 + cell;
                    int xw = t - y;
                    int fy = (d & 2) ? (HH - 1 - y)  : y;
                    int fx = (d & 1) ? (WW - 1 - xw) : xw;
                    v = __ldcg((const uint4*)&d_xT16[fy][fx][b][q8 * 8]);
                }
                int r = i * 32 + b;
                *(uint4*)&As[r * AKH + 256 + q8 * 8] = v;
            }
        }
        __syncthreads();

        // ================= MMA mainloop =================
        float acc[2][10][4];
#pragma unroll
        for (int mi = 0; mi < 2; mi++)
#pragma unroll
            for (int ni = 0; ni < 10; ni++)
#pragma unroll
                for (int e = 0; e < 4; e++) acc[mi][ni][e] = 0.0f;

#pragma unroll 5
        for (int ks = 0; ks < 20; ks++) {
            const uint32_t kb = ks * 32;   // 16 halves = 32 bytes
            uint32_t a0[4], a1[4];
            ldsm_x4(a0[0], a0[1], a0[2], a0[3], aAddr0 + kb);
            ldsm_x4(a1[0], a1[1], a1[2], a1[3], aAddr1 + kb);
#pragma unroll
            for (int n2 = 0; n2 < 5; n2++) {
                uint32_t b0, b1, b2, b3;
                ldsm_x4(b0, b1, b2, b3, bAddr[n2] + kb);
#pragma unroll
                for (int mi = 0; mi < 2; mi++) {
                    uint32_t* af = mi ? a1 : a0;
                    asm volatile(
                        "mma.sync.aligned.m16n8k16.row.col.f32.f16.f16.f32 "
                        "{%0,%1,%2,%3}, {%4,%5,%6,%7}, {%8,%9}, {%0,%1,%2,%3};\n"
                        : "+f"(acc[mi][2*n2][0]), "+f"(acc[mi][2*n2][1]),
                          "+f"(acc[mi][2*n2][2]), "+f"(acc[mi][2*n2][3])
                        : "r"(af[0]), "r"(af[1]), "r"(af[2]), "r"(af[3]),
                          "r"(b0), "r"(b1));
                    asm volatile(
                        "mma.sync.aligned.m16n8k16.row.col.f32.f16.f16.f32 "
                        "{%0,%1,%2,%3}, {%4,%5,%6,%7}, {%8,%9}, {%0,%1,%2,%3};\n"
                        : "+f"(acc[mi][2*n2+1][0]), "+f"(acc[mi][2*n2+1][1]),
                          "+f"(acc[mi][2*n2+1][2]), "+f"(acc[mi][2*n2+1][3])
                        : "r"(af[0]), "r"(af[1]), "r"(af[2]), "r"(af[3]),
                          "r"(b2), "r"(b3));
                }
            }
        }
        __syncthreads();   // done reading As before overwriting with Csm

        // ================= spill C to smem =================
#pragma unroll
        for (int mi = 0; mi < 2; mi++) {
#pragma unroll
            for (int ni = 0; ni < 10; ni++) {
                int row = wm * 32 + mi * 16 + g;
                int col = wn * 80 + ni * 8 + tq * 2;
                *(float2*)&Csm[row * CPAD + col] =
                    make_float2(acc[mi][ni][0], acc[mi][ni][1]);
                *(float2*)&Csm[(row + 8) * CPAD + col] =
                    make_float2(acc[mi][ni][2], acc[mi][ni][3]);
            }
        }
        __syncthreads();

        // ================= LSTM epilogue =================
#pragma unroll
        for (int i = 0; i < 16; i++) {
            int r  = i * 8 + warp;
            int j  = lane;
            int cl = r >> 5, b = r & 31;
            int cell = mtile * 4 + cl;
            if (cell < len) {
                int y  = y0 + cell;
                int xw = t - y;
                const float* cr = &Csm[r * CPAD];
                float gi = cr[j]       + bsm[j];
                float gf = cr[32 + j]  + bsm[32 + j];
                float gg = cr[64 + j]  + bsm[64 + j];
                float go = cr[96 + j]  + bsm[96 + j];
                float gl = cr[128 + j] + bsm[128 + j];
                float iv = sig_f(gi);
                float fv = sig_f(gf);
                float gv = tanh_f(gg);
                float ov = sig_f(go);
                float lv = sig_f(gl);
                int oc = cb * 32 + j;
                float cup = (y  > 0) ? __ldcg(&d_c32[d][y - 1][xw][b][oc]) : 0.0f;
                float clf = (xw > 0) ? __ldcg(&d_c32[d][y][xw - 1][b][oc]) : 0.0f;
                float cn = fv * (lv * cup + (1.0f - lv) * clf) + iv * gv;
                float hn = ov * tanh_f(cn);
                unsigned short hraw = __half_as_ushort(__float2half(hn));
                asm volatile("st.global.cg.u16 [%0], %1;"
                             :: "l"(&d_h16[d][y][xw][b][oc]), "h"(hraw) : "memory");
                __stcg(&d_c32[d][y][xw][b][oc], cn);
                __stcg(&d_h32[d][y][xw][b][oc], hn);
            }
        }
        __syncthreads();   // all CTA threads done with state writes

        // ---- per-direction barrier: release-add, acquire-poll ----
        if (tid == 0) {
            int* bar = &d_bar[d * 32];
            asm volatile("red.release.gpu.add.s32 [%0], %1;"
                         :: "l"(bar), "r"(1) : "memory");
            const int target = 32 * (t + 1);
            int v;
            do {
                asm volatile("ld.acquire.gpu.b32 %0, [%1];"
                             : "=r"(v) : "l"(bar) : "memory");
            } while (v < target);
        }
        __syncthreads();
    }
}

// ---------------------------------------------------------------------------
// final transpose: h32[d][y][xw][b][oc] -> out[b][d][oc][y][xw]
// ---------------------------------------------------------------------------
__global__ void __launch_bounds__(256) finalize_kernel(float* __restrict__ out) {
    int bid = blockIdx.x;
    int occ = bid & 3;
    int b   = (bid >> 2) & 31;
    int y   = (bid >> 7) & 31;
    int d   = bid >> 12;

    __shared__ float sm[128][33];

    for (int i = threadIdx.x; i < 128 * 32; i += 256) {
        int xw = i >> 5;
        int j  = i & 31;
        sm[xw][j] = d_h32[d][y][xw][b][occ * 32 + j];
    }
    __syncthreads();
    for (int i = threadIdx.x; i < 32 * 128; i += 256) {
        int j  = i >> 7;
        int xw = i & 127;
        int oc = occ * 32 + j;
        out[(((size_t)(b * 4 + d) * OCC + oc) * HH + y) * WW + xw] = sm[xw][j];
    }
}

// ---------------------------------------------------------------------------
// launch
// ---------------------------------------------------------------------------
extern "C" void kernel_launch(void* const* d_in, const int* in_sizes, int n_in,
                              void* d_out, int out_size) {
    const float* x  = (const float*)d_in[0];
    const float* w0 = (const float*)d_in[1];
    const float* u0 = (const float*)d_in[2];
    const float* u1 = (const float*)d_in[3];
    const float* bb = (const float*)d_in[4];
    float* out = (float*)d_out;
    (void)in_sizes; (void)n_in; (void)out_size;

    cudaFuncSetAttribute(persist_kernel,
                         cudaFuncAttributeMaxDynamicSharedMemorySize, SMEM_BYTES);

    prep_x<<<(HH * WW * BQ * CINC + 255) / 256, 256>>>(x);
    prep_w<<<(NDIR * G5 * KKK + 255) / 256, 256>>>(w0, u0, u1);
    prep_b<<<(NDIR * G5 + 255) / 256, 256>>>(bb);

    persist_kernel<<<128, 256, SMEM_BYTES>>>();

    finalize_kernel<<<NDIR * HH * BQ * 4, 256>>>(out);
}

// round 8
// speedup vs baseline: 2.5564x; 1.1548x over previous
#include <cuda_runtime.h>
#include <cuda_fp16.h>
#include <math.h>
#include <stdint.h>

// Problem constants
#define BQ   32
#define CINC 64
#define HH   32
#define WW   128
#define OCC  128
#define G5   640
#define KKK  320     // K = 128 (h_up) + 128 (h_lf) + 64 (x)
#define NDIR 4
#define NDIAG (HH + WW - 1)   // 159

#define MTILE 128    // 4 cells x 32 batch
#define NTILE 160    // 5 gates x 32 channels (permuted)
#define AKH   328    // padded K stride (halves)
#define CPAD  164    // padded C stride (floats)

#define A_SM   (MTILE * AKH * 2)          // 83,968
#define B_SM   (NTILE * AKH * 2)          // 104,960
#define BIAS_SM (NTILE * 4)               // 640
#define CSTATE_SM (2 * 128 * 32 * 4)      // 32,768 (double-buffered c cache)
#define SMEM_BYTES (A_SM + B_SM + BIAS_SM + CSTATE_SM)   // 222,336

// -------- device scratch --------
__device__ __half d_xT16[HH][WW][BQ][CINC];
__device__ __half d_BpT[NDIR][G5][KKK];
__device__ float  d_biasP[NDIR][G5];
__device__ __half d_h16[NDIR][HH][WW][BQ][OCC];
__device__ float  d_h32[NDIR][HH][WW][BQ][OCC];
__device__ float  d_c32[NDIR][HH][WW][BQ][OCC];
__device__ int    d_bar[NDIR * 8 * 32];    // per-(dir,slot) counter, padded lines

// ---------------------------------------------------------------------------
// prep kernels
// ---------------------------------------------------------------------------
__global__ void prep_x(const float* __restrict__ x) {
    int i = blockIdx.x * blockDim.x + threadIdx.x;
    if (i >= HH * WW * BQ * CINC) return;
    int cin = i & 63;
    int b   = (i >> 6) & 31;
    int xw  = (i >> 11) & 127;
    int y   = i >> 18;
    ((__half*)d_xT16)[i] = __float2half(x[((b * CINC + cin) * HH + y) * WW + xw]);
}

__global__ void prep_w(const float* __restrict__ w0,
                       const float* __restrict__ u0,
                       const float* __restrict__ u1) {
    int i = blockIdx.x * blockDim.x + threadIdx.x;
    if (i >= NDIR * G5 * KKK) return;
    int k    = i % KKK;
    int pcol = (i / KKK) % G5;
    int d    = i / (G5 * KKK);
    int cbl  = pcol / NTILE;
    int rem  = pcol % NTILE;
    int gate = rem / 32;
    int lane = rem % 32;
    int gcol = gate * 128 + cbl * 32 + lane;
    float v;
    if (k < 128)        v = u0[(d * 128 + k) * G5 + gcol];
    else if (k < 256)   v = u1[(d * 128 + (k - 128)) * G5 + gcol];
    else                v = w0[(d * 64  + (k - 256)) * G5 + gcol];
    ((__half*)d_BpT)[i] = __float2half(v);
}

__global__ void prep_b(const float* __restrict__ bias) {
    int i = blockIdx.x * blockDim.x + threadIdx.x;
    if (i < NDIR * 8 * 32) d_bar[i] = 0;       // reset counters every replay
    if (i >= NDIR * G5) return;
    int pcol = i % G5;
    int d    = i / G5;
    int cbl  = pcol / NTILE;
    int rem  = pcol % NTILE;
    int gate = rem / 32;
    int lane = rem % 32;
    int gcol = gate * 128 + cbl * 32 + lane;
    d_biasP[d][pcol] = bias[d * G5 + gcol];
}

// ---------------------------------------------------------------------------
// fast device math / asm helpers
// ---------------------------------------------------------------------------
__device__ __forceinline__ float sig_f(float x) {
    return __fdividef(1.0f, 1.0f + __expf(-x));
}
__device__ __forceinline__ float tanh_f(float x) {
    float xc = fminf(fmaxf(x, -9.0f), 9.0f);
    float t  = __expf(2.0f * xc);
    return __fdividef(t - 1.0f, t + 1.0f);
}
__device__ __forceinline__ uint32_t smem_u32(const void* p) {
    return (uint32_t)__cvta_generic_to_shared(p);
}
__device__ __forceinline__ void ldsm_x4(uint32_t& r0, uint32_t& r1,
                                        uint32_t& r2, uint32_t& r3,
                                        uint32_t addr) {
    asm volatile("ldmatrix.sync.aligned.m8n8.x4.shared.b16 {%0,%1,%2,%3}, [%4];"
                 : "=r"(r0), "=r"(r1), "=r"(r2), "=r"(r3) : "r"(addr));
}
__device__ __forceinline__ void bar_add(int* p, int v) {
    asm volatile("red.release.gpu.add.s32 [%0], %1;" :: "l"(p), "r"(v) : "memory");
}
__device__ __forceinline__ int bar_ld(const int* p) {
    int v;
    asm volatile("ld.acquire.gpu.b32 %0, [%1];" : "=r"(v) : "l"(p) : "memory");
    return v;
}

// ---------------------------------------------------------------------------
// persistent wavefront kernel: 128 CTAs (4 dir x 4 cb x 8 slots), 1/SM.
// Slot m owns rows 4m..4m+3 for ALL diagonals; sync = neighbor flags only.
// ---------------------------------------------------------------------------
__global__ void __launch_bounds__(256, 1) persist_kernel() {
    const int bid   = blockIdx.x;
    const int d     = bid >> 5;
    const int cb    = (bid >> 3) & 3;
    const int slot  = bid & 7;
    const int tid   = threadIdx.x;

    extern __shared__ __align__(16) char smem_raw[];
    __half* As   = (__half*)smem_raw;                       // [128][AKH]
    __half* Bs   = As + MTILE * AKH;                        // [160][AKH]
    float*  bsm  = (float*)((char*)smem_raw + A_SM + B_SM); // [160]
    float*  csm  = bsm + NTILE;                             // [2][128][32]
    float*  Csm  = (float*)smem_raw;                        // [128][CPAD], overlaps As

    // ---- stage B slice + bias ONCE ----
    for (int c = tid; c < NTILE * 40; c += 256) {
        int n = c / 40;
        int q = c - n * 40;
        *(uint4*)&Bs[n * AKH + q * 8] =
            *(const uint4*)&d_BpT[d][cb * NTILE + n][q * 8];
    }
    for (int i = tid; i < NTILE; i += 256) bsm[i] = d_biasP[d][cb * NTILE + i];
    __syncthreads();

    int* barS = &d_bar[(d * 8 + slot) * 32];
    int* barP = barS - 32;

    // credit for skipped leading diagonals (t < 4*slot)
    if (tid == 0 && slot > 0) bar_add(barS, 4 * slot);

    const int warp  = tid >> 5;
    const int lane  = tid & 31;
    const int wm    = warp & 3;
    const int wn    = warp >> 2;
    const int g     = lane >> 2;
    const int tq    = lane & 3;
    const int lane7 = lane & 7;
    const int lb8   = (lane >> 3) & 1;
    const int lb16  = lane >> 4;

    const uint32_t aAddr0 =
        smem_u32(&As[(wm * 32 + lane7 + lb8 * 8) * AKH + lb16 * 8]);
    const uint32_t aAddr1 = aAddr0 + 16 * AKH * 2;
    uint32_t bAddr[5];
#pragma unroll
    for (int n2 = 0; n2 < 5; n2++)
        bAddr[n2] = smem_u32(
            &Bs[(wn * 80 + n2 * 16 + lb16 * 8 + lane7) * AKH + lb8 * 8]);

    // A-stage phase-A constants
    const int clA   = warp >> 1;
    const int bA0   = (warp & 1) * 16;
    const int selLf = (lane >= 16);
    const int koffA = (lane * 8) & 127;
    const int yA    = slot * 4 + clA;      // absolute row, constant

    const int t0 = 4 * slot;
    const int t1 = (4 * slot + 130 < NDIAG - 1) ? (4 * slot + 130) : (NDIAG - 1);

    for (int t = t0; t <= t1; t++) {
        // ---- wait: own slot peers + slot-1 done through diag t-1 ----
        if (tid == 0) {
            const int tgt = 4 * t;
            while (bar_ld(barS) < tgt) { }
            if (slot > 0) while (bar_ld(barP) < tgt) { }
        }
        __syncthreads();

        // ===== A-stage phase A: recurrent K (h_up | h_lf) =====
        {
            int x     = t - yA;
            bool valid = (x >= 0) && (x < WW);
            bool up_ok = valid && (yA > 0);
            bool lf_ok = valid && (x > 0);
            int yu = up_ok ? yA - 1 : 0;
            int xl = lf_ok ? x - 1 : 0;
            int xc = valid ? x : 0;
            const __half* pUp = &d_h16[d][yu][xc][0][0];
            const __half* pLf = &d_h16[d][yA][xl][0][0];
            const __half* pSel = selLf ? pLf : pUp;
            const bool pok = selLf ? lf_ok : up_ok;
#pragma unroll
            for (int i = 0; i < 16; i++) {
                int r = warp * 16 + i;
                uint4 v = make_uint4(0u, 0u, 0u, 0u);
                if (pok) v = __ldcg((const uint4*)(pSel + (bA0 + i) * 128 + koffA));
                *(uint4*)&As[r * AKH + lane * 8] = v;
            }
        }
        // ===== A-stage phase B: x slice (K 256..319) =====
        {
            int b  = tid >> 3;
            int q8 = tid & 7;
#pragma unroll
            for (int i = 0; i < 4; i++) {
                int y  = slot * 4 + i;
                int x  = t - y;
                uint4 v = make_uint4(0u, 0u, 0u, 0u);
                if (x >= 0 && x < WW) {
                    int fy = (d & 2) ? (HH - 1 - y) : y;
                    int fx = (d & 1) ? (WW - 1 - x) : x;
                    v = __ldcg((const uint4*)&d_xT16[fy][fx][b][q8 * 8]);
                }
                *(uint4*)&As[(i * 32 + b) * AKH + 256 + q8 * 8] = v;
            }
        }
        __syncthreads();

        // ===== MMA mainloop =====
        float acc[2][10][4];
#pragma unroll
        for (int mi = 0; mi < 2; mi++)
#pragma unroll
            for (int ni = 0; ni < 10; ni++)
#pragma unroll
                for (int e = 0; e < 4; e++) acc[mi][ni][e] = 0.0f;

#pragma unroll 5
        for (int ks = 0; ks < 20; ks++) {
            const uint32_t kb = ks * 32;
            uint32_t a0[4], a1[4];
            ldsm_x4(a0[0], a0[1], a0[2], a0[3], aAddr0 + kb);
            ldsm_x4(a1[0], a1[1], a1[2], a1[3], aAddr1 + kb);
#pragma unroll
            for (int n2 = 0; n2 < 5; n2++) {
                uint32_t b0, b1, b2, b3;
                ldsm_x4(b0, b1, b2, b3, bAddr[n2] + kb);
#pragma unroll
                for (int mi = 0; mi < 2; mi++) {
                    uint32_t* af = mi ? a1 : a0;
                    asm volatile(
                        "mma.sync.aligned.m16n8k16.row.col.f32.f16.f16.f32 "
                        "{%0,%1,%2,%3}, {%4,%5,%6,%7}, {%8,%9}, {%0,%1,%2,%3};\n"
                        : "+f"(acc[mi][2*n2][0]), "+f"(acc[mi][2*n2][1]),
                          "+f"(acc[mi][2*n2][2]), "+f"(acc[mi][2*n2][3])
                        : "r"(af[0]), "r"(af[1]), "r"(af[2]), "r"(af[3]),
                          "r"(b0), "r"(b1));
                    asm volatile(
                        "mma.sync.aligned.m16n8k16.row.col.f32.f16.f16.f32 "
                        "{%0,%1,%2,%3}, {%4,%5,%6,%7}, {%8,%9}, {%0,%1,%2,%3};\n"
                        : "+f"(acc[mi][2*n2+1][0]), "+f"(acc[mi][2*n2+1][1]),
                          "+f"(acc[mi][2*n2+1][2]), "+f"(acc[mi][2*n2+1][3])
                        : "r"(af[0]), "r"(af[1]), "r"(af[2]), "r"(af[3]),
                          "r"(b2), "r"(b3));
                }
            }
        }
        __syncthreads();   // done reading As before overwriting with Csm

        // ===== spill gates to smem =====
#pragma unroll
        for (int mi = 0; mi < 2; mi++) {
#pragma unroll
            for (int ni = 0; ni < 10; ni++) {
                int row = wm * 32 + mi * 16 + g;
                int col = wn * 80 + ni * 8 + tq * 2;
                *(float2*)&Csm[row * CPAD + col] =
                    make_float2(acc[mi][ni][0], acc[mi][ni][1]);
                *(float2*)&Csm[(row + 8) * CPAD + col] =
                    make_float2(acc[mi][ni][2], acc[mi][ni][3]);
            }
        }
        __syncthreads();

        // ===== LSTM epilogue: c-state from smem ring =====
        const float* csmPR = csm + ((t & 1) ^ 1) * (128 * 32);
        float*       csmPW = csm + (t & 1) * (128 * 32);
#pragma unroll
        for (int i = 0; i < 16; i++) {
            int r  = i * 8 + warp;
            int j  = lane;
            int cl = r >> 5, b = r & 31;
            int y  = slot * 4 + cl;
            int x  = t - y;
            if (x >= 0 && x < WW) {
                const float* cr = &Csm[r * CPAD];
                float gi = cr[j]       + bsm[j];
                float gf = cr[32 + j]  + bsm[32 + j];
                float gg = cr[64 + j]  + bsm[64 + j];
                float go = cr[96 + j]  + bsm[96 + j];
                float gl = cr[128 + j] + bsm[128 + j];
                float iv = sig_f(gi);
                float fv = sig_f(gf);
                float gv = tanh_f(gg);
                float ov = sig_f(go);
                float lv = sig_f(gl);
                int oc = cb * 32 + j;
                float clf = (x > 0) ? csmPR[r * 32 + j] : 0.0f;
                float cup;
                if (cl > 0)       cup = csmPR[(r - 32) * 32 + j];
                else if (y > 0)   cup = __ldcg(&d_c32[d][y - 1][x][b][oc]);
                else              cup = 0.0f;
                float cn = fv * (lv * cup + (1.0f - lv) * clf) + iv * gv;
                float hn = ov * tanh_f(cn);
                csmPW[r * 32 + j] = cn;
                if (cl == 3) __stcg(&d_c32[d][y][x][b][oc], cn);   // boundary publish
                __stcg(&d_h32[d][y][x][b][oc], hn);
                unsigned short hraw = __half_as_ushort(__float2half(hn));
                asm volatile("st.global.cg.u16 [%0], %1;"
                             :: "l"(&d_h16[d][y][x][b][oc]), "h"(hraw) : "memory");
            }
        }
        __syncthreads();   // all threads' stores issued before release

        if (tid == 0) bar_add(barS, 1);
    }

    // credit for skipped trailing diagonals
    if (tid == 0) {
        int tail = (NDIAG - 1) - t1;
        if (tail > 0) bar_add(barS, tail);
    }
}

// ---------------------------------------------------------------------------
// final transpose: h32[d][y][xw][b][oc] -> out[b][d][oc][y][xw]
// ---------------------------------------------------------------------------
__global__ void __launch_bounds__(256) finalize_kernel(float* __restrict__ out) {
    int bid = blockIdx.x;
    int occ = bid & 3;
    int b   = (bid >> 2) & 31;
    int y   = (bid >> 7) & 31;
    int d   = bid >> 12;

    __shared__ float sm[128][33];

    for (int i = threadIdx.x; i < 128 * 32; i += 256) {
        int xw = i >> 5;
        int j  = i & 31;
        sm[xw][j] = d_h32[d][y][xw][b][occ * 32 + j];
    }
    __syncthreads();
    for (int i = threadIdx.x; i < 32 * 128; i += 256) {
        int j  = i >> 7;
        int xw = i & 127;
        int oc = occ * 32 + j;
        out[(((size_t)(b * 4 + d) * OCC + oc) * HH + y) * WW + xw] = sm[xw][j];
    }
}

// ---------------------------------------------------------------------------
// launch
// ---------------------------------------------------------------------------
extern "C" void kernel_launch(void* const* d_in, const int* in_sizes, int n_in,
                              void* d_out, int out_size) {
    const float* x  = (const float*)d_in[0];
    const float* w0 = (const float*)d_in[1];
    const float* u0 = (const float*)d_in[2];
    const float* u1 = (const float*)d_in[3];
    const float* bb = (const float*)d_in[4];
    float* out = (float*)d_out;
    (void)in_sizes; (void)n_in; (void)out_size;

    cudaFuncSetAttribute(persist_kernel,
                         cudaFuncAttributeMaxDynamicSharedMemorySize, SMEM_BYTES);

    prep_x<<<(HH * WW * BQ * CINC + 255) / 256, 256>>>(x);
    prep_w<<<(NDIR * G5 * KKK + 255) / 256, 256>>>(w0, u0, u1);
    prep_b<<<(NDIR * G5 + 255) / 256, 256>>>(bb);

    persist_kernel<<<128, 256, SMEM_BYTES>>>();

    finalize_kernel<<<NDIR * HH * BQ * 4, 256>>>(out);
}